// round 7
// baseline (speedup 1.0000x reference)
#include <cuda_runtime.h>
#include <math.h>
#include <stdint.h>

// Problem shape (fixed by the reference)
#define BB 16
#define SS 2048
#define EE 512
#define HH 1024
#define NROWS (BB * SS)

// Scratch (allocation-free rule: __device__ globals)
__device__ float g_scores[(size_t)BB * SS * SS];  // 256 MB (P, tf32-rounded after softmax)
__device__ float g_attn  [(size_t)BB * SS * EE];
__device__ float g_x     [(size_t)BB * SS * EE];
__device__ float g_xtf   [(size_t)BB * SS * EE];  // tf32-rounded copy of x
__device__ float g_h     [(size_t)BB * SS * HH];  // tf32-rounded (gelu epilogue)
__device__ float g_ff    [(size_t)BB * SS * EE];
__device__ float g_vt    [(size_t)BB * SS * EE];  // V^T per batch, tf32-rounded
__device__ float g_w1t   [(size_t)EE * HH];       // tf32-rounded
__device__ float g_w2t   [(size_t)EE * HH];       // tf32-rounded
__device__ float g_qtf   [(size_t)BB * SS * EE];  // tf32-rounded q
__device__ float g_ktf   [(size_t)BB * SS * EE];  // tf32-rounded k

__device__ __forceinline__ float gelu_exact(float v) {
    return 0.5f * v * (1.0f + erff(v * 0.70710678118654752f));
}

// ============================ PTX helpers (base ISA only) ============================
__device__ __forceinline__ uint32_t smem_u32(const void* p) {
    uint32_t a;
    asm("{ .reg .u64 t; cvta.to.shared.u64 t, %1; cvt.u32.u64 %0, t; }"
        : "=r"(a) : "l"(p));
    return a;
}

__device__ __forceinline__ void cp_async16(uint32_t dst, const void* src) {
    asm volatile("cp.async.cg.shared.global [%0], [%1], 16;"
                 :: "r"(dst), "l"(src) : "memory");
}
__device__ __forceinline__ void cp_commit() {
    asm volatile("cp.async.commit_group;" ::: "memory");
}
template <int N>
__device__ __forceinline__ void cp_wait() {
    asm volatile("cp.async.wait_group %0;" :: "n"(N) : "memory");
}

__device__ __forceinline__ uint32_t f2tf(float f) {
    uint32_t u;
    asm("cvt.rna.tf32.f32 %0, %1;" : "=r"(u) : "f"(f));
    return u;
}
__device__ __forceinline__ float f2tf_f(float f) {
    return __uint_as_float(f2tf(f));
}

__device__ __forceinline__ void mma_tf32(float* c, const uint32_t* a, const uint32_t* b) {
    asm volatile(
        "mma.sync.aligned.m16n8k8.row.col.f32.tf32.tf32.f32 "
        "{%0,%1,%2,%3}, {%4,%5,%6,%7}, {%8,%9}, {%0,%1,%2,%3};"
        : "+f"(c[0]), "+f"(c[1]), "+f"(c[2]), "+f"(c[3])
        : "r"(a[0]), "r"(a[1]), "r"(a[2]), "r"(a[3]), "r"(b[0]), "r"(b[1]));
}

// ============================ GEMM kernel ============================
// D = A @ B^T, A [*, K] row-major, B [*, K] row-major (NT).
// Operands are PRE-ROUNDED to tf32 bit patterns; inner loop is raw LDS + MMA.
// CTA tile 128x128, BK=32, 3-stage cp.async pipeline.
// 8 warps: wm in {0,1} (64 rows each), wn in {0..3} (32 cols each).
// EPI: 0 = alpha*acc, 1 = bias + exact GELU (tf32-rounded out), 2 = bias
#define BK 32
#define ROWPAD 36                  // floats per smem row (bank-spread + 16B aligned)
#define STAGE_F (2 * 128 * ROWPAD) // floats per stage (A+B)
#define GEMM_SMEM (3 * STAGE_F * 4)

template <int EPI>
__global__ __launch_bounds__(256, 1)
void gemm_mma_kernel(const float* __restrict__ A, const float* __restrict__ B,
                     float* __restrict__ C, int ldC, long long cBatch,
                     int aBatchRows, int bBatchRows, int K,
                     const float* __restrict__ bias, float alpha) {
    extern __shared__ float smem[];
    const int tid = threadIdx.x;
    const int bz = blockIdx.z;
    const int mBase = bz * aBatchRows + blockIdx.y * 128;
    const int nBase = bz * bBatchRows + blockIdx.x * 128;

    // loader mapping: each thread copies 4 float4 for A and 4 for B
    const int lr = tid >> 1;               // row 0..127
    const int lq = (tid & 1) * 4;          // float4 index base 0 or 4
    const float* aSrc = A + (long long)(mBase + lr) * K + lq * 4;
    const float* bSrc = B + (long long)(nBase + lr) * K + lq * 4;
    const uint32_t sBase = smem_u32(smem);
    const uint32_t aDst = sBase + (lr * ROWPAD + lq * 4) * 4;
    const uint32_t bDst = aDst + 128 * ROWPAD * 4;

    const int T = K / BK;

    // prologue: stages 0,1
    #pragma unroll
    for (int t = 0; t < 2; t++) {
        const uint32_t so = t * STAGE_F * 4;
        #pragma unroll
        for (int i = 0; i < 4; i++) {
            cp_async16(aDst + so + i * 16, aSrc + t * BK + i * 4);
            cp_async16(bDst + so + i * 16, bSrc + t * BK + i * 4);
        }
        cp_commit();
    }

    const int lane = tid & 31, warp = tid >> 5;
    const int wm = warp & 1, wn = warp >> 1;   // wm: 0..1, wn: 0..3
    const int gid = lane >> 2, tq = lane & 3;

    float acc[4][4][4];
    #pragma unroll
    for (int i = 0; i < 4; i++)
        #pragma unroll
        for (int j = 0; j < 4; j++)
            #pragma unroll
            for (int r = 0; r < 4; r++) acc[i][j][r] = 0.0f;

    for (int t = 0; t < T; t++) {
        cp_wait<1>();
        __syncthreads();

        // issue loads for t+2 (slot consumed at t-1; all warps past it)
        if (t + 2 < T) {
            const uint32_t so = ((t + 2) % 3) * STAGE_F * 4;
            const int kt = (t + 2) * BK;
            #pragma unroll
            for (int i = 0; i < 4; i++) {
                cp_async16(aDst + so + i * 16, aSrc + kt + i * 4);
                cp_async16(bDst + so + i * 16, bSrc + kt + i * 4);
            }
        }
        cp_commit();

        const uint32_t* sA = (const uint32_t*)(smem + (t % 3) * STAGE_F);
        const uint32_t* sB = sA + 128 * ROWPAD;

        #pragma unroll
        for (int ks = 0; ks < 4; ks++) {
            const int k0 = ks * 8;
            uint32_t af[4][4], bf[4][2];
            #pragma unroll
            for (int i = 0; i < 4; i++) {
                const uint32_t* pa = sA + (wm * 64 + i * 16 + gid) * ROWPAD + k0 + tq;
                af[i][0] = pa[0];
                af[i][1] = pa[8 * ROWPAD];
                af[i][2] = pa[4];
                af[i][3] = pa[8 * ROWPAD + 4];
            }
            #pragma unroll
            for (int j = 0; j < 4; j++) {
                const uint32_t* pb = sB + (wn * 32 + j * 8 + gid) * ROWPAD + k0 + tq;
                bf[j][0] = pb[0];
                bf[j][1] = pb[4];
            }
            #pragma unroll
            for (int i = 0; i < 4; i++)
                #pragma unroll
                for (int j = 0; j < 4; j++)
                    mma_tf32(acc[i][j], af[i], bf[j]);
        }
        __syncthreads();
    }

    // epilogue
    float* Cb = C + (long long)bz * cBatch;
    float2 bv[4];
    if (EPI != 0) {
        #pragma unroll
        for (int j = 0; j < 4; j++)
            bv[j] = *(const float2*)(bias + blockIdx.x * 128 + wn * 32 + j * 8 + 2 * tq);
    }
    #pragma unroll
    for (int i = 0; i < 4; i++) {
        const int row = blockIdx.y * 128 + wm * 64 + i * 16 + gid;
        #pragma unroll
        for (int j = 0; j < 4; j++) {
            const int col = blockIdx.x * 128 + wn * 32 + j * 8 + 2 * tq;
            float v0 = acc[i][j][0], v1 = acc[i][j][1];
            float v2 = acc[i][j][2], v3 = acc[i][j][3];
            if (EPI == 0) {
                v0 *= alpha; v1 *= alpha; v2 *= alpha; v3 *= alpha;
            } else if (EPI == 1) {
                v0 = f2tf_f(gelu_exact(v0 + bv[j].x));
                v1 = f2tf_f(gelu_exact(v1 + bv[j].y));
                v2 = f2tf_f(gelu_exact(v2 + bv[j].x));
                v3 = f2tf_f(gelu_exact(v3 + bv[j].y));
            } else {
                v0 += bv[j].x; v1 += bv[j].y;
                v2 += bv[j].x; v3 += bv[j].y;
            }
            *(float2*)(Cb + (long long)row * ldC + col)       = make_float2(v0, v1);
            *(float2*)(Cb + (long long)(row + 8) * ldC + col) = make_float2(v2, v3);
        }
    }
}

// ============================ elementwise tf32 round ============================
__global__ __launch_bounds__(256)
void round_tf32_kernel(const float* __restrict__ in, float* __restrict__ out) {
    const size_t i = ((size_t)blockIdx.x * 256 + threadIdx.x) * 4;
    float4 v = *(const float4*)(in + i);
    v.x = f2tf_f(v.x); v.y = f2tf_f(v.y);
    v.z = f2tf_f(v.z); v.w = f2tf_f(v.w);
    *(float4*)(out + i) = v;
}

// ============================ transpose (tf32-rounded output) ============================
__global__ __launch_bounds__(256)
void transpose_kernel(const float* __restrict__ in, float* __restrict__ out,
                      int rows, int cols) {
    __shared__ float t[32][33];
    const long long boff = (long long)blockIdx.z * rows * cols;
    in += boff; out += boff;
    const int c0 = blockIdx.x * 32, r0 = blockIdx.y * 32;
    const int tx = threadIdx.x & 31, ty = threadIdx.x >> 5;  // 32 x 8
    #pragma unroll
    for (int i = 0; i < 4; i++)
        t[ty + 8 * i][tx] = in[(long long)(r0 + ty + 8 * i) * cols + c0 + tx];
    __syncthreads();
    #pragma unroll
    for (int i = 0; i < 4; i++)
        out[(long long)(c0 + ty + 8 * i) * rows + r0 + tx] = f2tf_f(t[tx][ty + 8 * i]);
}

// ============================ softmax (tf32-rounded output) ============================
__global__ __launch_bounds__(256)
void softmax_kernel(float* __restrict__ P) {
    float* row = P + (size_t)blockIdx.x * 2048;
    const int tid = threadIdx.x;

    float4 v0 = ((float4*)row)[tid];
    float4 v1 = ((float4*)row)[tid + 256];

    float m = fmaxf(fmaxf(fmaxf(v0.x, v0.y), fmaxf(v0.z, v0.w)),
                    fmaxf(fmaxf(v1.x, v1.y), fmaxf(v1.z, v1.w)));

    __shared__ float smax[8];
    __shared__ float ssum[8];
    const int wid = tid >> 5, lane = tid & 31;

    #pragma unroll
    for (int o = 16; o > 0; o >>= 1)
        m = fmaxf(m, __shfl_xor_sync(0xffffffffu, m, o));
    if (lane == 0) smax[wid] = m;
    __syncthreads();
    m = smax[0];
    #pragma unroll
    for (int i = 1; i < 8; i++) m = fmaxf(m, smax[i]);

    v0.x = __expf(v0.x - m); v0.y = __expf(v0.y - m);
    v0.z = __expf(v0.z - m); v0.w = __expf(v0.w - m);
    v1.x = __expf(v1.x - m); v1.y = __expf(v1.y - m);
    v1.z = __expf(v1.z - m); v1.w = __expf(v1.w - m);

    float s = v0.x + v0.y + v0.z + v0.w + v1.x + v1.y + v1.z + v1.w;
    #pragma unroll
    for (int o = 16; o > 0; o >>= 1)
        s += __shfl_xor_sync(0xffffffffu, s, o);
    if (lane == 0) ssum[wid] = s;
    __syncthreads();
    s = ssum[0];
    #pragma unroll
    for (int i = 1; i < 8; i++) s += ssum[i];

    const float inv = 1.0f / s;
    v0.x = f2tf_f(v0.x * inv); v0.y = f2tf_f(v0.y * inv);
    v0.z = f2tf_f(v0.z * inv); v0.w = f2tf_f(v0.w * inv);
    v1.x = f2tf_f(v1.x * inv); v1.y = f2tf_f(v1.y * inv);
    v1.z = f2tf_f(v1.z * inv); v1.w = f2tf_f(v1.w * inv);

    ((float4*)row)[tid]       = v0;
    ((float4*)row)[tid + 256] = v1;
}

// ============================ add + LayerNorm ============================
// Optional second output: tf32-rounded copy (for feeding the next GEMM).
__global__ __launch_bounds__(128)
void add_ln_kernel(const float* __restrict__ A, const float* __restrict__ Bv,
                   const float* __restrict__ gamma, const float* __restrict__ beta,
                   float* __restrict__ out, float* __restrict__ out_tf) {
    const size_t base = (size_t)blockIdx.x * 512;
    const int tid = threadIdx.x;

    float4 a = ((const float4*)(A + base))[tid];
    float4 b = ((const float4*)(Bv + base))[tid];
    float v0 = a.x + b.x, v1 = a.y + b.y, v2 = a.z + b.z, v3 = a.w + b.w;

    float s  = v0 + v1 + v2 + v3;
    float sq = v0 * v0 + v1 * v1 + v2 * v2 + v3 * v3;

    __shared__ float ss[4];
    __shared__ float sk[4];
    const int wid = tid >> 5, lane = tid & 31;
    #pragma unroll
    for (int o = 16; o > 0; o >>= 1) {
        s  += __shfl_xor_sync(0xffffffffu, s, o);
        sq += __shfl_xor_sync(0xffffffffu, sq, o);
    }
    if (lane == 0) { ss[wid] = s; sk[wid] = sq; }
    __syncthreads();
    s  = ss[0] + ss[1] + ss[2] + ss[3];
    sq = sk[0] + sk[1] + sk[2] + sk[3];

    const float mu  = s * (1.0f / 512.0f);
    const float var = sq * (1.0f / 512.0f) - mu * mu;
    const float rs  = rsqrtf(var + 1e-5f);

    float4 g  = ((const float4*)gamma)[tid];
    float4 be = ((const float4*)beta)[tid];

    float4 o;
    o.x = (v0 - mu) * rs * g.x + be.x;
    o.y = (v1 - mu) * rs * g.y + be.y;
    o.z = (v2 - mu) * rs * g.z + be.z;
    o.w = (v3 - mu) * rs * g.w + be.w;
    ((float4*)(out + base))[tid] = o;
    if (out_tf) {
        float4 ot;
        ot.x = f2tf_f(o.x); ot.y = f2tf_f(o.y);
        ot.z = f2tf_f(o.z); ot.w = f2tf_f(o.w);
        ((float4*)(out_tf + base))[tid] = ot;
    }
}

// ============================ host ============================
extern "C" void kernel_launch(void* const* d_in, const int* in_sizes, int n_in,
                              void* d_out, int out_size) {
    const float* q     = (const float*)d_in[0];
    const float* k     = (const float*)d_in[1];
    const float* v     = (const float*)d_in[2];
    const float* ln1_g = (const float*)d_in[3];
    const float* ln1_b = (const float*)d_in[4];
    const float* w1    = (const float*)d_in[5];
    const float* b1    = (const float*)d_in[6];
    const float* w2    = (const float*)d_in[7];
    const float* b2    = (const float*)d_in[8];
    const float* ln3_g = (const float*)d_in[9];
    const float* ln3_b = (const float*)d_in[10];
    float* out = (float*)d_out;

    float *scores, *attn, *x, *xtf, *h, *ff, *vt, *w1t, *w2t, *qtf, *ktf;
    cudaGetSymbolAddress((void**)&scores, g_scores);
    cudaGetSymbolAddress((void**)&attn,   g_attn);
    cudaGetSymbolAddress((void**)&x,      g_x);
    cudaGetSymbolAddress((void**)&xtf,    g_xtf);
    cudaGetSymbolAddress((void**)&h,      g_h);
    cudaGetSymbolAddress((void**)&ff,     g_ff);
    cudaGetSymbolAddress((void**)&vt,     g_vt);
    cudaGetSymbolAddress((void**)&w1t,    g_w1t);
    cudaGetSymbolAddress((void**)&w2t,    g_w2t);
    cudaGetSymbolAddress((void**)&qtf,    g_qtf);
    cudaGetSymbolAddress((void**)&ktf,    g_ktf);

    cudaFuncSetAttribute(gemm_mma_kernel<0>,
                         cudaFuncAttributeMaxDynamicSharedMemorySize, GEMM_SMEM);
    cudaFuncSetAttribute(gemm_mma_kernel<1>,
                         cudaFuncAttributeMaxDynamicSharedMemorySize, GEMM_SMEM);
    cudaFuncSetAttribute(gemm_mma_kernel<2>,
                         cudaFuncAttributeMaxDynamicSharedMemorySize, GEMM_SMEM);

    const float alpha = 1.0f / sqrtf((float)EE);

    // 0) producers: tf32-rounded operand copies
    round_tf32_kernel<<<(size_t)NROWS * EE / 1024, 256>>>(q, qtf);
    round_tf32_kernel<<<(size_t)NROWS * EE / 1024, 256>>>(k, ktf);
    transpose_kernel<<<dim3(EE / 32, SS / 32, BB), 256>>>(v, vt, SS, EE);
    transpose_kernel<<<dim3(HH / 32, EE / 32, 1), 256>>>(w1, w1t, EE, HH);
    transpose_kernel<<<dim3(EE / 32, HH / 32, 1), 256>>>(w2, w2t, HH, EE);

    // 1) scores = alpha * q @ k^T   [per batch 2048x2048, K=512]
    gemm_mma_kernel<0><<<dim3(SS / 128, SS / 128, BB), 256, GEMM_SMEM>>>(
        qtf, ktf, scores, SS, (long long)SS * SS, SS, SS, EE, nullptr, alpha);

    // 2) softmax rows (writes tf32-rounded P)
    softmax_kernel<<<NROWS, 256>>>(scores);

    // 3) attn = P @ Vt^T            [per batch 2048x512, K=2048]
    gemm_mma_kernel<0><<<dim3(EE / 128, SS / 128, BB), 256, GEMM_SMEM>>>(
        scores, vt, attn, EE, (long long)SS * EE, SS, EE, SS, nullptr, 1.0f);

    // 4) x = LN(q + attn)  (+ tf32 copy)
    add_ln_kernel<<<NROWS, 128>>>(q, attn, ln1_g, ln1_b, x, xtf);

    // 5) h = gelu(x @ w1t^T + b1)   [32768x1024, K=512] (tf32-rounded out)
    gemm_mma_kernel<1><<<dim3(HH / 128, NROWS / 128, 1), 256, GEMM_SMEM>>>(
        xtf, w1t, h, HH, 0LL, 0, 0, EE, b1, 1.0f);

    // 6) ff = h @ w2t^T + b2        [32768x512, K=1024]
    gemm_mma_kernel<2><<<dim3(EE / 128, NROWS / 128, 1), 256, GEMM_SMEM>>>(
        h, w2t, ff, EE, 0LL, 0, 0, HH, b2, 1.0f);

    // 7) out = LN(x + ff)
    add_ln_kernel<<<NROWS, 128>>>(x, ff, ln3_g, ln3_b, out, nullptr);
}

// round 9
// speedup vs baseline: 1.0814x; 1.0814x over previous
#include <cuda_runtime.h>
#include <math.h>
#include <stdint.h>

// Problem shape (fixed by the reference)
#define BB 16
#define SS 2048
#define EE 512
#define HH 1024
#define NROWS (BB * SS)

// Scratch (allocation-free rule: __device__ globals)
__device__ float g_scores[(size_t)BB * SS * SS];  // 256 MB
__device__ float g_attn  [(size_t)BB * SS * EE];
__device__ float g_x     [(size_t)BB * SS * EE];
__device__ float g_h     [(size_t)BB * SS * HH];
__device__ float g_ff    [(size_t)BB * SS * EE];
__device__ float g_vt    [(size_t)BB * SS * EE];  // V^T per batch [E, S]
__device__ float g_w1t   [(size_t)EE * HH];       // [H, E]
__device__ float g_w2t   [(size_t)EE * HH];       // [E, H]

__device__ __forceinline__ float gelu_exact(float v) {
    return 0.5f * v * (1.0f + erff(v * 0.70710678118654752f));
}

// ============================ PTX helpers (base ISA only) ============================
__device__ __forceinline__ uint32_t smem_u32(const void* p) {
    uint32_t a;
    asm("{ .reg .u64 t; cvta.to.shared.u64 t, %1; cvt.u32.u64 %0, t; }"
        : "=r"(a) : "l"(p));
    return a;
}

__device__ __forceinline__ void cp_async16(uint32_t dst, const void* src) {
    asm volatile("cp.async.cg.shared.global [%0], [%1], 16;"
                 :: "r"(dst), "l"(src) : "memory");
}
__device__ __forceinline__ void cp_commit() {
    asm volatile("cp.async.commit_group;" ::: "memory");
}
template <int N>
__device__ __forceinline__ void cp_wait() {
    asm volatile("cp.async.wait_group %0;" :: "n"(N) : "memory");
}

__device__ __forceinline__ uint32_t f2tf(float f) {
    uint32_t u;
    asm("cvt.rna.tf32.f32 %0, %1;" : "=r"(u) : "f"(f));
    return u;
}

__device__ __forceinline__ void mma_tf32(float* c, const uint32_t* a, const uint32_t* b) {
    asm volatile(
        "mma.sync.aligned.m16n8k8.row.col.f32.tf32.tf32.f32 "
        "{%0,%1,%2,%3}, {%4,%5,%6,%7}, {%8,%9}, {%0,%1,%2,%3};"
        : "+f"(c[0]), "+f"(c[1]), "+f"(c[2]), "+f"(c[3])
        : "r"(a[0]), "r"(a[1]), "r"(a[2]), "r"(a[3]), "r"(b[0]), "r"(b[1]));
}

// ============================ GEMM kernel ============================
// D = A @ B^T, A [*, K] row-major, B [*, K] row-major (NT).
// CTA tile 128x128, BK=32, 2-stage cp.async pipeline (73.7KB smem ->
// 2 CTAs/SM for latency hiding), tf32 mma.sync with in-loop cvt.
// 8 warps: wm in {0,1} (64 rows each), wn in {0..3} (32 cols each).
// EPI: 0 = alpha*acc, 1 = bias + exact GELU, 2 = bias
#define BK 32
#define ROWPAD 36                  // floats per smem row (bank-spread + 16B aligned)
#define STAGE_F (2 * 128 * ROWPAD) // floats per stage (A+B)
#define GEMM_SMEM (2 * STAGE_F * 4)

template <int EPI>
__global__ __launch_bounds__(256, 2)
void gemm_mma_kernel(const float* __restrict__ A, const float* __restrict__ B,
                     float* __restrict__ C, int ldC, long long cBatch,
                     int aBatchRows, int bBatchRows, int K,
                     const float* __restrict__ bias, float alpha) {
    extern __shared__ float smem[];
    const int tid = threadIdx.x;
    const int bz = blockIdx.z;
    const int mBase = bz * aBatchRows + blockIdx.y * 128;
    const int nBase = bz * bBatchRows + blockIdx.x * 128;

    // loader mapping: each thread copies 4 float4 for A and 4 for B
    const int lr = tid >> 1;               // row 0..127
    const int lq = (tid & 1) * 4;          // float4 index base 0 or 4
    const float* aSrc = A + (long long)(mBase + lr) * K + lq * 4;
    const float* bSrc = B + (long long)(nBase + lr) * K + lq * 4;
    const uint32_t sBase = smem_u32(smem);
    const uint32_t aDst = sBase + (lr * ROWPAD + lq * 4) * 4;
    const uint32_t bDst = aDst + 128 * ROWPAD * 4;

    const int T = K / BK;

    // prologue: stage 0
    #pragma unroll
    for (int i = 0; i < 4; i++) {
        cp_async16(aDst + i * 16, aSrc + i * 4);
        cp_async16(bDst + i * 16, bSrc + i * 4);
    }
    cp_commit();

    const int lane = tid & 31, warp = tid >> 5;
    const int wm = warp & 1, wn = warp >> 1;   // wm: 0..1, wn: 0..3
    const int gid = lane >> 2, tq = lane & 3;

    float acc[4][4][4];
    #pragma unroll
    for (int i = 0; i < 4; i++)
        #pragma unroll
        for (int j = 0; j < 4; j++)
            #pragma unroll
            for (int r = 0; r < 4; r++) acc[i][j][r] = 0.0f;

    for (int t = 0; t < T; t++) {
        // issue loads for t+1 into the other buffer (its prior contents were
        // consumed at t-1; the __syncthreads at the end of that iteration
        // guarantees all warps are done with it)
        if (t + 1 < T) {
            const uint32_t so = ((t + 1) & 1) * STAGE_F * 4;
            const int kt = (t + 1) * BK;
            #pragma unroll
            for (int i = 0; i < 4; i++) {
                cp_async16(aDst + so + i * 16, aSrc + kt + i * 4);
                cp_async16(bDst + so + i * 16, bSrc + kt + i * 4);
            }
        }
        cp_commit();          // always commit (empty group on last iter)
        cp_wait<1>();         // stage t complete; stage t+1 in flight
        __syncthreads();

        const float* sA = smem + (t & 1) * STAGE_F;
        const float* sB = sA + 128 * ROWPAD;

        #pragma unroll
        for (int ks = 0; ks < 4; ks++) {
            const int k0 = ks * 8;
            uint32_t af[4][4], bf[4][2];
            #pragma unroll
            for (int i = 0; i < 4; i++) {
                const float* pa = sA + (wm * 64 + i * 16 + gid) * ROWPAD + k0 + tq;
                af[i][0] = f2tf(pa[0]);
                af[i][1] = f2tf(pa[8 * ROWPAD]);
                af[i][2] = f2tf(pa[4]);
                af[i][3] = f2tf(pa[8 * ROWPAD + 4]);
            }
            #pragma unroll
            for (int j = 0; j < 4; j++) {
                const float* pb = sB + (wn * 32 + j * 8 + gid) * ROWPAD + k0 + tq;
                bf[j][0] = f2tf(pb[0]);
                bf[j][1] = f2tf(pb[4]);
            }
            #pragma unroll
            for (int i = 0; i < 4; i++)
                #pragma unroll
                for (int j = 0; j < 4; j++)
                    mma_tf32(acc[i][j], af[i], bf[j]);
        }
        __syncthreads();
    }

    // epilogue
    float* Cb = C + (long long)bz * cBatch;
    float2 bv[4];
    if (EPI != 0) {
        #pragma unroll
        for (int j = 0; j < 4; j++)
            bv[j] = *(const float2*)(bias + blockIdx.x * 128 + wn * 32 + j * 8 + 2 * tq);
    }
    #pragma unroll
    for (int i = 0; i < 4; i++) {
        const int row = blockIdx.y * 128 + wm * 64 + i * 16 + gid;
        #pragma unroll
        for (int j = 0; j < 4; j++) {
            const int col = blockIdx.x * 128 + wn * 32 + j * 8 + 2 * tq;
            float v0 = acc[i][j][0], v1 = acc[i][j][1];
            float v2 = acc[i][j][2], v3 = acc[i][j][3];
            if (EPI == 0) {
                v0 *= alpha; v1 *= alpha; v2 *= alpha; v3 *= alpha;
            } else if (EPI == 1) {
                v0 = gelu_exact(v0 + bv[j].x); v1 = gelu_exact(v1 + bv[j].y);
                v2 = gelu_exact(v2 + bv[j].x); v3 = gelu_exact(v3 + bv[j].y);
            } else {
                v0 += bv[j].x; v1 += bv[j].y;
                v2 += bv[j].x; v3 += bv[j].y;
            }
            *(float2*)(Cb + (long long)row * ldC + col)       = make_float2(v0, v1);
            *(float2*)(Cb + (long long)(row + 8) * ldC + col) = make_float2(v2, v3);
        }
    }
}

// ============================ transpose ============================
__global__ __launch_bounds__(256)
void transpose_kernel(const float* __restrict__ in, float* __restrict__ out,
                      int rows, int cols) {
    __shared__ float t[32][33];
    const long long boff = (long long)blockIdx.z * rows * cols;
    in += boff; out += boff;
    const int c0 = blockIdx.x * 32, r0 = blockIdx.y * 32;
    const int tx = threadIdx.x & 31, ty = threadIdx.x >> 5;  // 32 x 8
    #pragma unroll
    for (int i = 0; i < 4; i++)
        t[ty + 8 * i][tx] = in[(long long)(r0 + ty + 8 * i) * cols + c0 + tx];
    __syncthreads();
    #pragma unroll
    for (int i = 0; i < 4; i++)
        out[(long long)(c0 + ty + 8 * i) * rows + r0 + tx] = t[tx][ty + 8 * i];
}

// ============================ softmax ============================
__global__ __launch_bounds__(256)
void softmax_kernel(float* __restrict__ P) {
    float* row = P + (size_t)blockIdx.x * 2048;
    const int tid = threadIdx.x;

    float4 v0 = ((float4*)row)[tid];
    float4 v1 = ((float4*)row)[tid + 256];

    float m = fmaxf(fmaxf(fmaxf(v0.x, v0.y), fmaxf(v0.z, v0.w)),
                    fmaxf(fmaxf(v1.x, v1.y), fmaxf(v1.z, v1.w)));

    __shared__ float smax[8];
    __shared__ float ssum[8];
    const int wid = tid >> 5, lane = tid & 31;

    #pragma unroll
    for (int o = 16; o > 0; o >>= 1)
        m = fmaxf(m, __shfl_xor_sync(0xffffffffu, m, o));
    if (lane == 0) smax[wid] = m;
    __syncthreads();
    m = smax[0];
    #pragma unroll
    for (int i = 1; i < 8; i++) m = fmaxf(m, smax[i]);

    v0.x = __expf(v0.x - m); v0.y = __expf(v0.y - m);
    v0.z = __expf(v0.z - m); v0.w = __expf(v0.w - m);
    v1.x = __expf(v1.x - m); v1.y = __expf(v1.y - m);
    v1.z = __expf(v1.z - m); v1.w = __expf(v1.w - m);

    float s = v0.x + v0.y + v0.z + v0.w + v1.x + v1.y + v1.z + v1.w;
    #pragma unroll
    for (int o = 16; o > 0; o >>= 1)
        s += __shfl_xor_sync(0xffffffffu, s, o);
    if (lane == 0) ssum[wid] = s;
    __syncthreads();
    s = ssum[0];
    #pragma unroll
    for (int i = 1; i < 8; i++) s += ssum[i];

    const float inv = 1.0f / s;
    v0.x *= inv; v0.y *= inv; v0.z *= inv; v0.w *= inv;
    v1.x *= inv; v1.y *= inv; v1.z *= inv; v1.w *= inv;

    ((float4*)row)[tid]       = v0;
    ((float4*)row)[tid + 256] = v1;
}

// ============================ add + LayerNorm ============================
__global__ __launch_bounds__(128)
void add_ln_kernel(const float* __restrict__ A, const float* __restrict__ Bv,
                   const float* __restrict__ gamma, const float* __restrict__ beta,
                   float* __restrict__ out) {
    const size_t base = (size_t)blockIdx.x * 512;
    const int tid = threadIdx.x;

    float4 a = ((const float4*)(A + base))[tid];
    float4 b = ((const float4*)(Bv + base))[tid];
    float v0 = a.x + b.x, v1 = a.y + b.y, v2 = a.z + b.z, v3 = a.w + b.w;

    float s  = v0 + v1 + v2 + v3;
    float sq = v0 * v0 + v1 * v1 + v2 * v2 + v3 * v3;

    __shared__ float ss[4];
    __shared__ float sk[4];
    const int wid = tid >> 5, lane = tid & 31;
    #pragma unroll
    for (int o = 16; o > 0; o >>= 1) {
        s  += __shfl_xor_sync(0xffffffffu, s, o);
        sq += __shfl_xor_sync(0xffffffffu, sq, o);
    }
    if (lane == 0) { ss[wid] = s; sk[wid] = sq; }
    __syncthreads();
    s  = ss[0] + ss[1] + ss[2] + ss[3];
    sq = sk[0] + sk[1] + sk[2] + sk[3];

    const float mu  = s * (1.0f / 512.0f);
    const float var = sq * (1.0f / 512.0f) - mu * mu;
    const float rs  = rsqrtf(var + 1e-5f);

    float4 g  = ((const float4*)gamma)[tid];
    float4 be = ((const float4*)beta)[tid];

    float4 o;
    o.x = (v0 - mu) * rs * g.x + be.x;
    o.y = (v1 - mu) * rs * g.y + be.y;
    o.z = (v2 - mu) * rs * g.z + be.z;
    o.w = (v3 - mu) * rs * g.w + be.w;
    ((float4*)(out + base))[tid] = o;
}

// ============================ host ============================
extern "C" void kernel_launch(void* const* d_in, const int* in_sizes, int n_in,
                              void* d_out, int out_size) {
    const float* q     = (const float*)d_in[0];
    const float* k     = (const float*)d_in[1];
    const float* v     = (const float*)d_in[2];
    const float* ln1_g = (const float*)d_in[3];
    const float* ln1_b = (const float*)d_in[4];
    const float* w1    = (const float*)d_in[5];
    const float* b1    = (const float*)d_in[6];
    const float* w2    = (const float*)d_in[7];
    const float* b2    = (const float*)d_in[8];
    const float* ln3_g = (const float*)d_in[9];
    const float* ln3_b = (const float*)d_in[10];
    float* out = (float*)d_out;

    float *scores, *attn, *x, *h, *ff, *vt, *w1t, *w2t;
    cudaGetSymbolAddress((void**)&scores, g_scores);
    cudaGetSymbolAddress((void**)&attn,   g_attn);
    cudaGetSymbolAddress((void**)&x,      g_x);
    cudaGetSymbolAddress((void**)&h,      g_h);
    cudaGetSymbolAddress((void**)&ff,     g_ff);
    cudaGetSymbolAddress((void**)&vt,     g_vt);
    cudaGetSymbolAddress((void**)&w1t,    g_w1t);
    cudaGetSymbolAddress((void**)&w2t,    g_w2t);

    cudaFuncSetAttribute(gemm_mma_kernel<0>,
                         cudaFuncAttributeMaxDynamicSharedMemorySize, GEMM_SMEM);
    cudaFuncSetAttribute(gemm_mma_kernel<1>,
                         cudaFuncAttributeMaxDynamicSharedMemorySize, GEMM_SMEM);
    cudaFuncSetAttribute(gemm_mma_kernel<2>,
                         cudaFuncAttributeMaxDynamicSharedMemorySize, GEMM_SMEM);

    const float alpha = 1.0f / sqrtf((float)EE);

    // 0) transposes: V -> Vt (per batch), w1 -> w1t, w2 -> w2t
    transpose_kernel<<<dim3(EE / 32, SS / 32, BB), 256>>>(v, vt, SS, EE);
    transpose_kernel<<<dim3(HH / 32, EE / 32, 1), 256>>>(w1, w1t, EE, HH);
    transpose_kernel<<<dim3(EE / 32, HH / 32, 1), 256>>>(w2, w2t, HH, EE);

    // 1) scores = alpha * q @ k^T   [per batch 2048x2048, K=512]
    gemm_mma_kernel<0><<<dim3(SS / 128, SS / 128, BB), 256, GEMM_SMEM>>>(
        q, k, scores, SS, (long long)SS * SS, SS, SS, EE, nullptr, alpha);

    // 2) softmax rows
    softmax_kernel<<<NROWS, 256>>>(scores);

    // 3) attn = P @ Vt^T            [per batch 2048x512, K=2048]
    gemm_mma_kernel<0><<<dim3(EE / 128, SS / 128, BB), 256, GEMM_SMEM>>>(
        scores, vt, attn, EE, (long long)SS * EE, SS, EE, SS, nullptr, 1.0f);

    // 4) x = LN(q + attn)
    add_ln_kernel<<<NROWS, 128>>>(q, attn, ln1_g, ln1_b, x);

    // 5) h = gelu(x @ w1t^T + b1)   [32768x1024, K=512]
    gemm_mma_kernel<1><<<dim3(HH / 128, NROWS / 128, 1), 256, GEMM_SMEM>>>(
        x, w1t, h, HH, 0LL, 0, 0, EE, b1, 1.0f);

    // 6) ff = h @ w2t^T + b2        [32768x512, K=1024]
    gemm_mma_kernel<2><<<dim3(EE / 128, NROWS / 128, 1), 256, GEMM_SMEM>>>(
        h, w2t, ff, EE, 0LL, 0, 0, HH, b2, 1.0f);

    // 7) out = LN(x + ff)
    add_ln_kernel<<<NROWS, 128>>>(x, ff, ln3_g, ln3_b, out);
}